// round 8
// baseline (speedup 1.0000x reference)
#include <cuda_runtime.h>
#include <cuda_fp16.h>
#include <mma.h>
#include <math.h>

using namespace nvcuda;

#define NN   50000
#define NNP  50048           // padded to multiple of 64
#define EE   800000
#define INF_ 128
#define H    8
#define HIDD 32
#define OUTD 16
#define C1   (H*HIDD)   // 256
#define C2   (H*OUTD)   // 128

// ---------------- scratch (device globals, zero-initialized) ----------------
__device__ __half g_x16  [(size_t)NNP * INF_];
__device__ __half g_W1_16[INF_ * C1];
__device__ __half g_W2_16[C1 * C2];
__device__ __half g_feat1[(size_t)NNP * C1];
__device__ __half g_agg1 [(size_t)NNP * C1];   // fp16: GEMM2 input
__device__ __half g_feat2[(size_t)NNP * C2];
__device__ float  g_el   [NN * H];
__device__ float  g_er   [NN * H];
__device__ int    g_csr  [EE];
__device__ int    g_rowstart[NN + 1];
__device__ int    g_cnt  [NN];

// ---------------- merged: zero histogram + fp16 conversions ------------------
__global__ void k_convert_zero(const float* __restrict__ x, const float* __restrict__ W1,
                               const float* __restrict__ W2) {
    int i = blockIdx.x * blockDim.x + threadIdx.x;
    if (i < NN)        g_cnt[i] = 0;
    if (i < NN * INF_) g_x16[i] = __float2half_rn(x[i]);
    if (i < INF_ * C1) g_W1_16[i] = __float2half_rn(W1[i]);
    if (i < C1 * C2)   g_W2_16[i] = __float2half_rn(W2[i]);
}

__global__ void k_hist(const int* __restrict__ dst) {
    int e = blockIdx.x * blockDim.x + threadIdx.x;
    if (e < EE) atomicAdd(&g_cnt[dst[e]], 1);
}

// scan body executed by one 256-thread block (inside the merged GEMM kernel)
__device__ void scan_body() {
    const int T = 256;
    const int CH = (NN + T - 1) / T;     // 196
    int t = threadIdx.x;
    int base = t * CH;
    int s = 0;
#pragma unroll 4
    for (int i = 0; i < CH; i++) {
        int idx = base + i;
        if (idx < NN) s += g_cnt[idx];
    }
    __shared__ int sh[T];
    sh[t] = s;
    __syncthreads();
    for (int off = 1; off < T; off <<= 1) {
        int v = (t >= off) ? sh[t - off] : 0;
        __syncthreads();
        sh[t] += v;
        __syncthreads();
    }
    int run = sh[t] - s;
    for (int i = 0; i < CH; i++) {
        int idx = base + i;
        if (idx < NN) {
            int c = g_cnt[idx];
            g_rowstart[idx] = run;
            g_cnt[idx] = run;
            run += c;
        }
    }
    if (t == 0) g_rowstart[NN] = EE;
}

__global__ void k_scatter(const int* __restrict__ src, const int* __restrict__ dst) {
    int e = blockIdx.x * blockDim.x + threadIdx.x;
    if (e >= EE) return;
    int p = atomicAdd(&g_cnt[dst[e]], 1);
    g_csr[p] = src[e];
}

// ---------------- tensor-core GEMM + attention epilogue ----------------------
// If SCAN: the LAST block runs the CSR scan instead (concurrent, independent).
template<int K, int NC, int D, bool SCAN>
__global__ void gemm_att_wmma(const __half* __restrict__ A, const __half* __restrict__ Wm,
                              const float* __restrict__ al, const float* __restrict__ ar,
                              __half* __restrict__ feat, float* __restrict__ el,
                              float* __restrict__ er, int n)
{
    if (SCAN && blockIdx.x == gridDim.x - 1) { scan_body(); return; }

    extern __shared__ float sm[];    // 64 * NC floats
    constexpr int NSPAN = NC / 2;
    constexpr int NFRAG = NSPAN / 16;

    int wid = threadIdx.x >> 5;
    int warp_m = wid & 3;
    int warp_n = wid >> 2;
    int m0 = blockIdx.x * 64 + warp_m * 16;

    wmma::fragment<wmma::accumulator, 16, 16, 16, float> c[NFRAG];
#pragma unroll
    for (int f = 0; f < NFRAG; f++) wmma::fill_fragment(c[f], 0.f);

    for (int k = 0; k < K; k += 16) {
        wmma::fragment<wmma::matrix_a, 16, 16, 16, __half, wmma::row_major> a;
        wmma::load_matrix_sync(a, A + (size_t)m0 * K + k, K);
#pragma unroll
        for (int f = 0; f < NFRAG; f++) {
            wmma::fragment<wmma::matrix_b, 16, 16, 16, __half, wmma::row_major> b;
            wmma::load_matrix_sync(b, Wm + (size_t)k * NC + warp_n * NSPAN + f * 16, NC);
            wmma::mma_sync(c[f], a, b, c[f]);
        }
    }

#pragma unroll
    for (int f = 0; f < NFRAG; f++)
        wmma::store_matrix_sync(sm + warp_m * 16 * NC + warp_n * NSPAN + f * 16,
                                c[f], NC, wmma::mem_row_major);
    __syncthreads();

    constexpr int RPT = NC / 4;
    int j = threadIdx.x % NC;
    int r0 = (threadIdx.x / NC) * RPT;
    float alj = al[j], arj = ar[j];
    int head = j / D;
    for (int r = r0; r < r0 + RPT; r++) {
        int row = blockIdx.x * 64 + r;
        float v = sm[r * NC + j];
        bool valid = row < n;
        if (valid) feat[(size_t)row * NC + j] = __float2half_rn(v);
        float ev = v * alj;
        float rv = v * arj;
#pragma unroll
        for (int off = D / 2; off > 0; off >>= 1) {
            ev += __shfl_xor_sync(0xffffffffu, ev, off);
            rv += __shfl_xor_sync(0xffffffffu, rv, off);
        }
        if ((j % D) == 0 && valid) {
            el[row * H + head] = ev;
            er[row * H + head] = rv;
        }
    }
}

// ---------------- fused per-node softmax + aggregate (single pass) ----------
// One warp per dst node, WPN=1 (R7 showed splitting regresses). 4-edge unroll
// with csr-index prefetch one stage ahead (hides one L2 round trip per group).
template<int DT, bool ELU, bool FINAL>
__global__ void node_aggregate(const __half* __restrict__ feat,
                               const float* __restrict__ el,
                               const float* __restrict__ er,
                               const float* __restrict__ bias,
                               void* __restrict__ outp)
{
    int d = blockIdx.x * (blockDim.x >> 5) + (threadIdx.x >> 5);
    if (d >= NN) return;
    int lane = threadIdx.x & 31;
    int head = lane >> 2;
    constexpr int V = DT / 32;        // 8 or 4
    constexpr int NH2 = V / 2;        // 4 or 2

    int beg = g_rowstart[d], end = g_rowstart[d + 1];
    int cnt = end - beg;

    float sum = 0.f;
    float acc[V];
#pragma unroll
    for (int k = 0; k < V; k++) acc[k] = 0.f;

    float erv = (cnt > 0) ? er[d * H + head] : 0.f;

    int n4end = beg + (cnt & ~3);
    int i = beg;
    int s0, s1, s2, s3;
    if (i < n4end) {
        s0 = g_csr[i]; s1 = g_csr[i+1]; s2 = g_csr[i+2]; s3 = g_csr[i+3];
    }
    for (; i < n4end; i += 4) {
        int c0 = s0, c1 = s1, c2 = s2, c3 = s3;
        if (i + 4 < n4end) {     // prefetch next group's indices
            s0 = g_csr[i+4]; s1 = g_csr[i+5]; s2 = g_csr[i+6]; s3 = g_csr[i+7];
        }
        float l0 = el[c0 * H + head];
        float l1 = el[c1 * H + head];
        float l2 = el[c2 * H + head];
        float l3 = el[c3 * H + head];
        __half2 v0[NH2], v1[NH2], v2[NH2], v3[NH2];
        if (V == 8) {
            *(uint4*)v0 = *(const uint4*)((const __half2*)(feat + (size_t)c0 * DT) + lane * NH2);
            *(uint4*)v1 = *(const uint4*)((const __half2*)(feat + (size_t)c1 * DT) + lane * NH2);
            *(uint4*)v2 = *(const uint4*)((const __half2*)(feat + (size_t)c2 * DT) + lane * NH2);
            *(uint4*)v3 = *(const uint4*)((const __half2*)(feat + (size_t)c3 * DT) + lane * NH2);
        } else {
            *(uint2*)v0 = *(const uint2*)((const __half2*)(feat + (size_t)c0 * DT) + lane * NH2);
            *(uint2*)v1 = *(const uint2*)((const __half2*)(feat + (size_t)c1 * DT) + lane * NH2);
            *(uint2*)v2 = *(const uint2*)((const __half2*)(feat + (size_t)c2 * DT) + lane * NH2);
            *(uint2*)v3 = *(const uint2*)((const __half2*)(feat + (size_t)c3 * DT) + lane * NH2);
        }
        l0 += erv; l1 += erv; l2 += erv; l3 += erv;
        l0 = l0 > 0.f ? l0 : 0.2f * l0;
        l1 = l1 > 0.f ? l1 : 0.2f * l1;
        l2 = l2 > 0.f ? l2 : 0.2f * l2;
        l3 = l3 > 0.f ? l3 : 0.2f * l3;
        float w0 = __expf(l0), w1 = __expf(l1), w2 = __expf(l2), w3 = __expf(l3);
        sum += (w0 + w1) + (w2 + w3);
#pragma unroll
        for (int k = 0; k < NH2; k++) {
            float2 a0 = __half22float2(v0[k]);
            float2 a1 = __half22float2(v1[k]);
            float2 a2 = __half22float2(v2[k]);
            float2 a3 = __half22float2(v3[k]);
            acc[k*2+0] += w0*a0.x + w1*a1.x + w2*a2.x + w3*a3.x;
            acc[k*2+1] += w0*a0.y + w1*a1.y + w2*a2.y + w3*a3.y;
        }
    }
    for (; i < end; i++) {
        int s = g_csr[i];
        float l = el[s * H + head] + erv;
        l = l > 0.f ? l : 0.2f * l;
        float wgt = __expf(l);
        sum += wgt;
        __half2 v[NH2];
        if (V == 8)
            *(uint4*)v = *(const uint4*)((const __half2*)(feat + (size_t)s * DT) + lane * NH2);
        else
            *(uint2*)v = *(const uint2*)((const __half2*)(feat + (size_t)s * DT) + lane * NH2);
#pragma unroll
        for (int k = 0; k < NH2; k++) {
            float2 a = __half22float2(v[k]);
            acc[k*2+0] += wgt * a.x;
            acc[k*2+1] += wgt * a.y;
        }
    }

    float inv = (cnt > 0) ? 1.f / sum : 0.f;

    float vals[V];
#pragma unroll
    for (int k = 0; k < V; k++) {
        float v = acc[k] * inv + bias[lane * V + k];
        vals[k] = ELU ? (v > 0.f ? v : expm1f(v)) : v;
    }

    if (!FINAL) {
        __half2 hv[NH2];
#pragma unroll
        for (int k = 0; k < NH2; k++)
            hv[k] = __floats2half2_rn(vals[k*2+0], vals[k*2+1]);
        __half* op = (__half*)outp + (size_t)d * DT + lane * V;
        if (V == 8) *(uint4*)op = *(uint4*)hv;
        else        *(uint2*)op = *(uint2*)hv;
    } else {
        // DT=128, V=4: head-mean via xor-reduce over head lanes
#pragma unroll
        for (int off = 4; off <= 16; off <<= 1) {
#pragma unroll
            for (int k = 0; k < V; k++)
                vals[k] += __shfl_xor_sync(0xffffffffu, vals[k], off);
        }
        if (lane < 4) {
            float4 o = make_float4(vals[0] * 0.125f, vals[1] * 0.125f,
                                   vals[2] * 0.125f, vals[3] * 0.125f);
            ((float4*)((float*)outp + (size_t)d * OUTD))[lane] = o;
        }
    }
}

// ---------------- launch ----------------------------------------------------
extern "C" void kernel_launch(void* const* d_in, const int* in_sizes, int n_in,
                              void* d_out, int out_size)
{
    const float* x   = (const float*)d_in[0];
    const float* W1  = (const float*)d_in[1];
    const float* al1 = (const float*)d_in[2];
    const float* ar1 = (const float*)d_in[3];
    const float* b1  = (const float*)d_in[4];
    const float* W2  = (const float*)d_in[5];
    const float* al2 = (const float*)d_in[6];
    const float* ar2 = (const float*)d_in[7];
    const float* b2  = (const float*)d_in[8];
    const int*   src = (const int*)d_in[9];
    const int*   dst = (const int*)d_in[10];
    float* out = (float*)d_out;

    __half *x16, *W1h, *W2h, *feat1, *agg1, *feat2;
    float *el, *er;
    cudaGetSymbolAddress((void**)&x16,   g_x16);
    cudaGetSymbolAddress((void**)&W1h,   g_W1_16);
    cudaGetSymbolAddress((void**)&W2h,   g_W2_16);
    cudaGetSymbolAddress((void**)&feat1, g_feat1);
    cudaGetSymbolAddress((void**)&agg1,  g_agg1);
    cudaGetSymbolAddress((void**)&feat2, g_feat2);
    cudaGetSymbolAddress((void**)&el,    g_el);
    cudaGetSymbolAddress((void**)&er,    g_er);

    static bool attrDone = false;
    if (!attrDone) {
        cudaFuncSetAttribute((const void*)gemm_att_wmma<INF_, C1, HIDD, true>,
                             cudaFuncAttributeMaxDynamicSharedMemorySize, 64 * C1 * 4);
        cudaFuncSetAttribute((const void*)gemm_att_wmma<C1, C2, OUTD, false>,
                             cudaFuncAttributeMaxDynamicSharedMemorySize, 64 * C2 * 4);
        attrDone = true;
    }

    const int eBlocks    = (EE + 255) / 256;
    const int gemmBlocks = NNP / 64;          // 782
    const int nodeBlocks = (NN + 7) / 8;

    // K1: zero histogram + fp16 converts (independent writes, one grid)
    k_convert_zero<<<(NN*INF_ + 255)/256, 256>>>(x, W1, W2);
    // K2: dst histogram
    k_hist<<<eBlocks, 256>>>(dst);
    // K3: GEMM1 (needs converts) + CSR scan as last block (needs hist) — concurrent
    gemm_att_wmma<INF_, C1, HIDD, true><<<gemmBlocks + 1, 256, 64*C1*4>>>(
        x16, W1h, al1, ar1, feat1, el, er, NN);
    // K4: scatter (needs scan)
    k_scatter<<<eBlocks, 256>>>(src, dst);
    // K5: layer-1 aggregate (needs CSR + feat1)
    node_aggregate<C1, true, false><<<nodeBlocks, 256>>>(feat1, el, er, b1, agg1);
    // K6: GEMM2
    gemm_att_wmma<C1, C2, OUTD, false><<<gemmBlocks, 256, 64*C2*4>>>(
        agg1, W2h, al2, ar2, feat2, el, er, NN);
    // K7: layer-2 aggregate + head-mean
    node_aggregate<C2, false, true><<<nodeBlocks, 256>>>(feat2, el, er, b2, out);
}

// round 9
// speedup vs baseline: 1.0514x; 1.0514x over previous
#include <cuda_runtime.h>
#include <cuda_fp16.h>
#include <mma.h>
#include <math.h>

using namespace nvcuda;

#define NN   50000
#define NNP  50048           // padded to multiple of 64
#define EE   800000
#define INF_ 128
#define H    8
#define HIDD 32
#define OUTD 16
#define C1   (H*HIDD)   // 256
#define C2   (H*OUTD)   // 128

// ---------------- scratch (device globals, zero-initialized) ----------------
__device__ __half g_x16  [(size_t)NNP * INF_];
__device__ __half g_W1_16[INF_ * C1];
__device__ __half g_W2_16[C1 * C2];
__device__ __half g_feat1[(size_t)NNP * C1];
__device__ __half g_agg1 [(size_t)NNP * C1];   // fp16: GEMM2 input
__device__ __half g_feat2[(size_t)NNP * C2];
__device__ float  g_el   [NN * H];
__device__ float  g_er   [NN * H];
__device__ int    g_csr  [EE];        // src per CSR position
__device__ int    g_cdst [EE];        // dst per CSR position (for layer-2 weights)
__device__ float  g_w1   [(size_t)EE * H];   // softmax numerators, CSR order
__device__ float  g_w2   [(size_t)EE * H];
__device__ int    g_rowstart[NN + 1];
__device__ int    g_cnt  [NN];

// ---------------- CSR build --------------------------------------------------
__global__ void k_zero_cnt() {
    int i = blockIdx.x * blockDim.x + threadIdx.x;
    if (i < NN) g_cnt[i] = 0;
}
__global__ void k_hist(const int* __restrict__ dst) {
    int e = blockIdx.x * blockDim.x + threadIdx.x;
    if (e < EE) atomicAdd(&g_cnt[dst[e]], 1);
}
__global__ void k_scan() {
    const int T = 1024;
    const int CH = (NN + T - 1) / T;
    int t = threadIdx.x;
    int base = t * CH;
    int s = 0;
#pragma unroll 4
    for (int i = 0; i < CH; i++) {
        int idx = base + i;
        if (idx < NN) s += g_cnt[idx];
    }
    __shared__ int sh[T];
    sh[t] = s;
    __syncthreads();
    for (int off = 1; off < T; off <<= 1) {
        int v = (t >= off) ? sh[t - off] : 0;
        __syncthreads();
        sh[t] += v;
        __syncthreads();
    }
    int run = sh[t] - s;
    for (int i = 0; i < CH; i++) {
        int idx = base + i;
        if (idx < NN) {
            int c = g_cnt[idx];
            g_rowstart[idx] = run;
            g_cnt[idx] = run;
            run += c;
        }
    }
    if (t == 0) g_rowstart[NN] = EE;
}

// compute exp(leaky(el[s]+er[d])) for all 8 heads -> out[p*8 .. p*8+7]
__device__ __forceinline__ void edge_weights(int s, int d, float* __restrict__ out) {
    const float4* lp = (const float4*)(g_el + (size_t)s * H);
    const float4* rp = (const float4*)(g_er + (size_t)d * H);
    float4 a0 = lp[0], a1 = lp[1], b0 = rp[0], b1 = rp[1];
    float l[8] = {a0.x+b0.x, a0.y+b0.y, a0.z+b0.z, a0.w+b0.w,
                  a1.x+b1.x, a1.y+b1.y, a1.z+b1.z, a1.w+b1.w};
    float w[8];
#pragma unroll
    for (int h = 0; h < 8; h++) {
        float v = l[h];
        v = v > 0.f ? v : 0.2f * v;
        w[h] = __expf(v);
    }
    ((float4*)out)[0] = make_float4(w[0], w[1], w[2], w[3]);
    ((float4*)out)[1] = make_float4(w[4], w[5], w[6], w[7]);
}

// scatter + layer-1 edge weights (gemm1 has already produced el/er)
__global__ void k_scatter_w(const int* __restrict__ src, const int* __restrict__ dst) {
    int e = blockIdx.x * blockDim.x + threadIdx.x;
    if (e >= EE) return;
    int s = src[e], d = dst[e];
    int p = atomicAdd(&g_cnt[d], 1);
    g_csr[p] = s;
    g_cdst[p] = d;
    edge_weights(s, d, g_w1 + (size_t)p * H);
}

// layer-2 edge weights (CSR order, after gemm2 refreshed el/er)
__global__ void k_edge_w2() {
    int i = blockIdx.x * blockDim.x + threadIdx.x;
    if (i >= EE) return;
    edge_weights(g_csr[i], g_cdst[i], g_w2 + (size_t)i * H);
}

// ---------------- fp16 conversions (x, W1, W2 in one kernel) -----------------
__global__ void k_convert(const float* __restrict__ x, const float* __restrict__ W1,
                          const float* __restrict__ W2) {
    int i = blockIdx.x * blockDim.x + threadIdx.x;
    if (i < NN * INF_) g_x16[i] = __float2half_rn(x[i]);
    if (i < INF_ * C1) g_W1_16[i] = __float2half_rn(W1[i]);
    if (i < C1 * C2)   g_W2_16[i] = __float2half_rn(W2[i]);
}

// ---------------- tensor-core GEMM + attention epilogue ----------------------
template<int K, int NC, int D>
__global__ void gemm_att_wmma(const __half* __restrict__ A, const __half* __restrict__ Wm,
                              const float* __restrict__ al, const float* __restrict__ ar,
                              __half* __restrict__ feat, float* __restrict__ el,
                              float* __restrict__ er, int n)
{
    extern __shared__ float sm[];    // 64 * NC floats
    constexpr int NSPAN = NC / 2;
    constexpr int NFRAG = NSPAN / 16;

    int wid = threadIdx.x >> 5;
    int warp_m = wid & 3;
    int warp_n = wid >> 2;
    int m0 = blockIdx.x * 64 + warp_m * 16;

    wmma::fragment<wmma::accumulator, 16, 16, 16, float> c[NFRAG];
#pragma unroll
    for (int f = 0; f < NFRAG; f++) wmma::fill_fragment(c[f], 0.f);

    for (int k = 0; k < K; k += 16) {
        wmma::fragment<wmma::matrix_a, 16, 16, 16, __half, wmma::row_major> a;
        wmma::load_matrix_sync(a, A + (size_t)m0 * K + k, K);
#pragma unroll
        for (int f = 0; f < NFRAG; f++) {
            wmma::fragment<wmma::matrix_b, 16, 16, 16, __half, wmma::row_major> b;
            wmma::load_matrix_sync(b, Wm + (size_t)k * NC + warp_n * NSPAN + f * 16, NC);
            wmma::mma_sync(c[f], a, b, c[f]);
        }
    }

#pragma unroll
    for (int f = 0; f < NFRAG; f++)
        wmma::store_matrix_sync(sm + warp_m * 16 * NC + warp_n * NSPAN + f * 16,
                                c[f], NC, wmma::mem_row_major);
    __syncthreads();

    constexpr int RPT = NC / 4;
    int j = threadIdx.x % NC;
    int r0 = (threadIdx.x / NC) * RPT;
    float alj = al[j], arj = ar[j];
    int head = j / D;
    for (int r = r0; r < r0 + RPT; r++) {
        int row = blockIdx.x * 64 + r;
        float v = sm[r * NC + j];
        bool valid = row < n;
        if (valid) feat[(size_t)row * NC + j] = __float2half_rn(v);
        float ev = v * alj;
        float rv = v * arj;
#pragma unroll
        for (int off = D / 2; off > 0; off >>= 1) {
            ev += __shfl_xor_sync(0xffffffffu, ev, off);
            rv += __shfl_xor_sync(0xffffffffu, rv, off);
        }
        if ((j % D) == 0 && valid) {
            el[row * H + head] = ev;
            er[row * H + head] = rv;
        }
    }
}

// ---------------- fused per-node aggregate (weights precomputed) -------------
// One warp per dst node. Weights w[i][head] are read sequentially (no
// dependence on csr value); only the feat gather remains a random hop.
template<int DT, bool ELU, bool FINAL>
__global__ void node_aggregate(const __half* __restrict__ feat,
                               const float* __restrict__ w,
                               const float* __restrict__ bias,
                               void* __restrict__ outp)
{
    int d = blockIdx.x * (blockDim.x >> 5) + (threadIdx.x >> 5);
    if (d >= NN) return;
    int lane = threadIdx.x & 31;
    int head = lane >> 2;
    constexpr int V = DT / 32;        // 8 or 4
    constexpr int NH2 = V / 2;        // 4 or 2

    int beg = g_rowstart[d], end = g_rowstart[d + 1];
    int cnt = end - beg;

    float sum = 0.f;
    float acc[V];
#pragma unroll
    for (int k = 0; k < V; k++) acc[k] = 0.f;

    int i = beg;
    for (; i + 3 < end; i += 4) {
        int s0 = g_csr[i+0], s1 = g_csr[i+1], s2 = g_csr[i+2], s3 = g_csr[i+3];
        float w0 = w[(size_t)(i+0) * H + head];
        float w1 = w[(size_t)(i+1) * H + head];
        float w2 = w[(size_t)(i+2) * H + head];
        float w3 = w[(size_t)(i+3) * H + head];
        __half2 v0[NH2], v1[NH2], v2[NH2], v3[NH2];
        if (V == 8) {
            *(uint4*)v0 = *(const uint4*)((const __half2*)(feat + (size_t)s0 * DT) + lane * NH2);
            *(uint4*)v1 = *(const uint4*)((const __half2*)(feat + (size_t)s1 * DT) + lane * NH2);
            *(uint4*)v2 = *(const uint4*)((const __half2*)(feat + (size_t)s2 * DT) + lane * NH2);
            *(uint4*)v3 = *(const uint4*)((const __half2*)(feat + (size_t)s3 * DT) + lane * NH2);
        } else {
            *(uint2*)v0 = *(const uint2*)((const __half2*)(feat + (size_t)s0 * DT) + lane * NH2);
            *(uint2*)v1 = *(const uint2*)((const __half2*)(feat + (size_t)s1 * DT) + lane * NH2);
            *(uint2*)v2 = *(const uint2*)((const __half2*)(feat + (size_t)s2 * DT) + lane * NH2);
            *(uint2*)v3 = *(const uint2*)((const __half2*)(feat + (size_t)s3 * DT) + lane * NH2);
        }
        sum += (w0 + w1) + (w2 + w3);
#pragma unroll
        for (int k = 0; k < NH2; k++) {
            float2 a0 = __half22float2(v0[k]);
            float2 a1 = __half22float2(v1[k]);
            float2 a2 = __half22float2(v2[k]);
            float2 a3 = __half22float2(v3[k]);
            acc[k*2+0] += w0*a0.x + w1*a1.x + w2*a2.x + w3*a3.x;
            acc[k*2+1] += w0*a0.y + w1*a1.y + w2*a2.y + w3*a3.y;
        }
    }
    for (; i < end; i++) {
        int s = g_csr[i];
        float wgt = w[(size_t)i * H + head];
        sum += wgt;
        __half2 v[NH2];
        if (V == 8)
            *(uint4*)v = *(const uint4*)((const __half2*)(feat + (size_t)s * DT) + lane * NH2);
        else
            *(uint2*)v = *(const uint2*)((const __half2*)(feat + (size_t)s * DT) + lane * NH2);
#pragma unroll
        for (int k = 0; k < NH2; k++) {
            float2 a = __half22float2(v[k]);
            acc[k*2+0] += wgt * a.x;
            acc[k*2+1] += wgt * a.y;
        }
    }

    float inv = (cnt > 0) ? 1.f / sum : 0.f;

    float vals[V];
#pragma unroll
    for (int k = 0; k < V; k++) {
        float v = acc[k] * inv + bias[lane * V + k];
        vals[k] = ELU ? (v > 0.f ? v : expm1f(v)) : v;
    }

    if (!FINAL) {
        __half2 hv[NH2];
#pragma unroll
        for (int k = 0; k < NH2; k++)
            hv[k] = __floats2half2_rn(vals[k*2+0], vals[k*2+1]);
        __half* op = (__half*)outp + (size_t)d * DT + lane * V;
        if (V == 8) *(uint4*)op = *(uint4*)hv;
        else        *(uint2*)op = *(uint2*)hv;
    } else {
        // DT=128, V=4: head-mean via xor-reduce over head lanes
#pragma unroll
        for (int off = 4; off <= 16; off <<= 1) {
#pragma unroll
            for (int k = 0; k < V; k++)
                vals[k] += __shfl_xor_sync(0xffffffffu, vals[k], off);
        }
        if (lane < 4) {
            float4 o = make_float4(vals[0] * 0.125f, vals[1] * 0.125f,
                                   vals[2] * 0.125f, vals[3] * 0.125f);
            ((float4*)((float*)outp + (size_t)d * OUTD))[lane] = o;
        }
    }
}

// ---------------- launch ----------------------------------------------------
extern "C" void kernel_launch(void* const* d_in, const int* in_sizes, int n_in,
                              void* d_out, int out_size)
{
    const float* x   = (const float*)d_in[0];
    const float* W1  = (const float*)d_in[1];
    const float* al1 = (const float*)d_in[2];
    const float* ar1 = (const float*)d_in[3];
    const float* b1  = (const float*)d_in[4];
    const float* W2  = (const float*)d_in[5];
    const float* al2 = (const float*)d_in[6];
    const float* ar2 = (const float*)d_in[7];
    const float* b2  = (const float*)d_in[8];
    const int*   src = (const int*)d_in[9];
    const int*   dst = (const int*)d_in[10];
    float* out = (float*)d_out;

    __half *x16, *W1h, *W2h, *feat1, *agg1, *feat2;
    float *el, *er, *w1, *w2;
    cudaGetSymbolAddress((void**)&x16,   g_x16);
    cudaGetSymbolAddress((void**)&W1h,   g_W1_16);
    cudaGetSymbolAddress((void**)&W2h,   g_W2_16);
    cudaGetSymbolAddress((void**)&feat1, g_feat1);
    cudaGetSymbolAddress((void**)&agg1,  g_agg1);
    cudaGetSymbolAddress((void**)&feat2, g_feat2);
    cudaGetSymbolAddress((void**)&el,    g_el);
    cudaGetSymbolAddress((void**)&er,    g_er);
    cudaGetSymbolAddress((void**)&w1,    g_w1);
    cudaGetSymbolAddress((void**)&w2,    g_w2);

    static bool attrDone = false;
    if (!attrDone) {
        cudaFuncSetAttribute((const void*)gemm_att_wmma<INF_, C1, HIDD>,
                             cudaFuncAttributeMaxDynamicSharedMemorySize, 64 * C1 * 4);
        cudaFuncSetAttribute((const void*)gemm_att_wmma<C1, C2, OUTD>,
                             cudaFuncAttributeMaxDynamicSharedMemorySize, 64 * C2 * 4);
        attrDone = true;
    }

    const int eBlocks    = (EE + 255) / 256;
    const int gemmBlocks = NNP / 64;
    const int nodeBlocks = (NN + 7) / 8;

    // CSR histogram + scan (weights need el/er, so scatter comes after gemm1)
    k_zero_cnt<<<(NN + 255)/256, 256>>>();
    k_hist<<<eBlocks, 256>>>(dst);
    k_scan<<<1, 1024>>>();

    // fp16 conversions + layer-1 GEMM (produces el/er for edge weights)
    k_convert<<<(NN*INF_ + 255)/256, 256>>>(x, W1, W2);
    gemm_att_wmma<INF_, C1, HIDD><<<gemmBlocks, 256, 64*C1*4>>>(x16, W1h, al1, ar1,
                                                                feat1, el, er, NN);

    // scatter + layer-1 edge weights in one pass
    k_scatter_w<<<eBlocks, 256>>>(src, dst);

    // layer-1 aggregate (weights sequential, feat gather only random hop)
    node_aggregate<C1, true, false><<<nodeBlocks, 256>>>(feat1, w1, b1, agg1);

    // layer-2 GEMM, then edge weights, then aggregate + head-mean
    gemm_att_wmma<C1, C2, OUTD><<<gemmBlocks, 256, 64*C2*4>>>(agg1, W2h, al2, ar2,
                                                              feat2, el, er, NN);
    k_edge_w2<<<eBlocks, 256>>>();
    node_aggregate<C2, false, true><<<nodeBlocks, 256>>>(feat2, w2, b2, out);
}

// round 10
// speedup vs baseline: 1.1166x; 1.0620x over previous
#include <cuda_runtime.h>
#include <cuda_fp16.h>
#include <mma.h>
#include <math.h>

using namespace nvcuda;

#define NN   50000
#define NNP  50048           // padded to multiple of 64
#define EE   800000
#define CSRP (EE + 4*NN)     // CSR capacity with per-row pad-to-4
#define INF_ 128
#define H    8
#define HIDD 32
#define OUTD 16
#define C1   (H*HIDD)   // 256
#define C2   (H*OUTD)   // 128

// ---------------- scratch (device globals, zero-initialized) ----------------
__device__ __half g_x16  [(size_t)NNP * INF_];
__device__ __half g_W1_16[INF_ * C1];
__device__ __half g_W2_16[C1 * C2];
__device__ __half g_feat1[(size_t)NNP * C1];   // row NN stays zero (dummy)
__device__ __half g_agg1 [(size_t)NNP * C1];
__device__ __half g_feat2[(size_t)NNP * C2];   // row NN stays zero (dummy)
__device__ float  g_el   [(NN + 1) * H];       // el[NN][*] = -1e30 (dummy)
__device__ float  g_er   [NN * H];
__device__ int    g_csr  [CSRP];
__device__ int    g_rowstart[NN + 1];
__device__ int    g_cnt  [NN];

// ---------------- merged: converts + zero cnt + csr dummy fill + dummy el ----
__global__ void k_convert(const float* __restrict__ x, const float* __restrict__ W1,
                          const float* __restrict__ W2) {
    int i = blockIdx.x * blockDim.x + threadIdx.x;
    if (i < NN * INF_) g_x16[i] = __float2half_rn(x[i]);
    if (i < INF_ * C1) g_W1_16[i] = __float2half_rn(W1[i]);
    if (i < C1 * C2)   g_W2_16[i] = __float2half_rn(W2[i]);
    if (i < NN)        g_cnt[i] = 0;
    if (i < CSRP)      g_csr[i] = NN;              // dummy src (zero weight)
    if (i < H)         g_el[NN * H + i] = -1e30f;  // dummy logit -> exp = 0
}

__global__ void k_hist(const int* __restrict__ dst) {
    int e = blockIdx.x * blockDim.x + threadIdx.x;
    if (e < EE) atomicAdd(&g_cnt[dst[e]], 1);
}

// exclusive scan of counts padded to multiples of 4
__global__ void k_scan() {
    const int T = 1024;
    const int CH = (NN + T - 1) / T;
    int t = threadIdx.x;
    int base = t * CH;
    int s = 0;
#pragma unroll 4
    for (int i = 0; i < CH; i++) {
        int idx = base + i;
        if (idx < NN) s += (g_cnt[idx] + 3) & ~3;
    }
    __shared__ int sh[T];
    sh[t] = s;
    __syncthreads();
    for (int off = 1; off < T; off <<= 1) {
        int v = (t >= off) ? sh[t - off] : 0;
        __syncthreads();
        sh[t] += v;
        __syncthreads();
    }
    int run = sh[t] - s;
    for (int i = 0; i < CH; i++) {
        int idx = base + i;
        if (idx < NN) {
            int pc = (g_cnt[idx] + 3) & ~3;
            g_rowstart[idx] = run;
            g_cnt[idx] = run;      // scatter cursor
            run += pc;
        }
    }
    if (t == T - 1) g_rowstart[NN] = run;
}

__global__ void k_scatter(const int* __restrict__ src, const int* __restrict__ dst) {
    int e = blockIdx.x * blockDim.x + threadIdx.x;
    if (e >= EE) return;
    int p = atomicAdd(&g_cnt[dst[e]], 1);
    g_csr[p] = src[e];
}

// ---------------- tensor-core GEMM + attention epilogue ----------------------
template<int K, int NC, int D>
__global__ void gemm_att_wmma(const __half* __restrict__ A, const __half* __restrict__ Wm,
                              const float* __restrict__ al, const float* __restrict__ ar,
                              __half* __restrict__ feat, float* __restrict__ el,
                              float* __restrict__ er, int n)
{
    extern __shared__ float sm[];    // 64 * NC floats
    constexpr int NSPAN = NC / 2;
    constexpr int NFRAG = NSPAN / 16;

    int wid = threadIdx.x >> 5;
    int warp_m = wid & 3;
    int warp_n = wid >> 2;
    int m0 = blockIdx.x * 64 + warp_m * 16;

    wmma::fragment<wmma::accumulator, 16, 16, 16, float> c[NFRAG];
#pragma unroll
    for (int f = 0; f < NFRAG; f++) wmma::fill_fragment(c[f], 0.f);

    for (int k = 0; k < K; k += 16) {
        wmma::fragment<wmma::matrix_a, 16, 16, 16, __half, wmma::row_major> a;
        wmma::load_matrix_sync(a, A + (size_t)m0 * K + k, K);
#pragma unroll
        for (int f = 0; f < NFRAG; f++) {
            wmma::fragment<wmma::matrix_b, 16, 16, 16, __half, wmma::row_major> b;
            wmma::load_matrix_sync(b, Wm + (size_t)k * NC + warp_n * NSPAN + f * 16, NC);
            wmma::mma_sync(c[f], a, b, c[f]);
        }
    }

#pragma unroll
    for (int f = 0; f < NFRAG; f++)
        wmma::store_matrix_sync(sm + warp_m * 16 * NC + warp_n * NSPAN + f * 16,
                                c[f], NC, wmma::mem_row_major);
    __syncthreads();

    constexpr int RPT = NC / 4;
    int j = threadIdx.x % NC;
    int r0 = (threadIdx.x / NC) * RPT;
    float alj = al[j], arj = ar[j];
    int head = j / D;
    for (int r = r0; r < r0 + RPT; r++) {
        int row = blockIdx.x * 64 + r;
        float v = sm[r * NC + j];
        bool valid = row < n;
        if (valid) feat[(size_t)row * NC + j] = __float2half_rn(v);
        float ev = v * alj;
        float rv = v * arj;
#pragma unroll
        for (int off = D / 2; off > 0; off >>= 1) {
            ev += __shfl_xor_sync(0xffffffffu, ev, off);
            rv += __shfl_xor_sync(0xffffffffu, rv, off);
        }
        if ((j % D) == 0 && valid) {
            el[row * H + head] = ev;
            er[row * H + head] = rv;
        }
    }
}

// ---------------- fused per-node softmax + aggregate (single pass) ----------
// One warp per dst node (R5 structure — proven best). CSR rows are padded to
// multiples of 4 with dummy index NN (weight 0, zero feat row), so the index
// load is one aligned int4 per group and there is no tail loop.
template<int DT, bool ELU, bool FINAL>
__global__ void node_aggregate(const __half* __restrict__ feat,
                               const float* __restrict__ el,
                               const float* __restrict__ er,
                               const float* __restrict__ bias,
                               void* __restrict__ outp)
{
    int d = blockIdx.x * (blockDim.x >> 5) + (threadIdx.x >> 5);
    if (d >= NN) return;
    int lane = threadIdx.x & 31;
    int head = lane >> 2;
    constexpr int V = DT / 32;        // 8 or 4
    constexpr int NH2 = V / 2;        // 4 or 2

    int beg = g_rowstart[d], end = g_rowstart[d + 1];

    float sum = 0.f;
    float acc[V];
#pragma unroll
    for (int k = 0; k < V; k++) acc[k] = 0.f;

    float erv = (beg < end) ? er[d * H + head] : 0.f;

    for (int i = beg; i < end; i += 4) {
        int4 sv = *(const int4*)(g_csr + i);     // aligned: beg % 4 == 0
        int s0 = sv.x, s1 = sv.y, s2 = sv.z, s3 = sv.w;
        float l0 = el[s0 * H + head];
        float l1 = el[s1 * H + head];
        float l2 = el[s2 * H + head];
        float l3 = el[s3 * H + head];
        __half2 v0[NH2], v1[NH2], v2[NH2], v3[NH2];
        if (V == 8) {
            *(uint4*)v0 = *(const uint4*)((const __half2*)(feat + (size_t)s0 * DT) + lane * NH2);
            *(uint4*)v1 = *(const uint4*)((const __half2*)(feat + (size_t)s1 * DT) + lane * NH2);
            *(uint4*)v2 = *(const uint4*)((const __half2*)(feat + (size_t)s2 * DT) + lane * NH2);
            *(uint4*)v3 = *(const uint4*)((const __half2*)(feat + (size_t)s3 * DT) + lane * NH2);
        } else {
            *(uint2*)v0 = *(const uint2*)((const __half2*)(feat + (size_t)s0 * DT) + lane * NH2);
            *(uint2*)v1 = *(const uint2*)((const __half2*)(feat + (size_t)s1 * DT) + lane * NH2);
            *(uint2*)v2 = *(const uint2*)((const __half2*)(feat + (size_t)s2 * DT) + lane * NH2);
            *(uint2*)v3 = *(const uint2*)((const __half2*)(feat + (size_t)s3 * DT) + lane * NH2);
        }
        l0 += erv; l1 += erv; l2 += erv; l3 += erv;
        l0 = l0 > 0.f ? l0 : 0.2f * l0;
        l1 = l1 > 0.f ? l1 : 0.2f * l1;
        l2 = l2 > 0.f ? l2 : 0.2f * l2;
        l3 = l3 > 0.f ? l3 : 0.2f * l3;
        float w0 = __expf(l0), w1 = __expf(l1), w2 = __expf(l2), w3 = __expf(l3);
        sum += (w0 + w1) + (w2 + w3);
#pragma unroll
        for (int k = 0; k < NH2; k++) {
            float2 a0 = __half22float2(v0[k]);
            float2 a1 = __half22float2(v1[k]);
            float2 a2 = __half22float2(v2[k]);
            float2 a3 = __half22float2(v3[k]);
            acc[k*2+0] += w0*a0.x + w1*a1.x + w2*a2.x + w3*a3.x;
            acc[k*2+1] += w0*a0.y + w1*a1.y + w2*a2.y + w3*a3.y;
        }
    }

    float inv = (beg < end) ? 1.f / sum : 0.f;

    float vals[V];
#pragma unroll
    for (int k = 0; k < V; k++) {
        float v = acc[k] * inv + bias[lane * V + k];
        vals[k] = ELU ? (v > 0.f ? v : expm1f(v)) : v;
    }

    if (!FINAL) {
        __half2 hv[NH2];
#pragma unroll
        for (int k = 0; k < NH2; k++)
            hv[k] = __floats2half2_rn(vals[k*2+0], vals[k*2+1]);
        __half* op = (__half*)outp + (size_t)d * DT + lane * V;
        if (V == 8) *(uint4*)op = *(uint4*)hv;
        else        *(uint2*)op = *(uint2*)hv;
    } else {
        // DT=128, V=4: head-mean via xor-reduce over head lanes
#pragma unroll
        for (int off = 4; off <= 16; off <<= 1) {
#pragma unroll
            for (int k = 0; k < V; k++)
                vals[k] += __shfl_xor_sync(0xffffffffu, vals[k], off);
        }
        if (lane < 4) {
            float4 o = make_float4(vals[0] * 0.125f, vals[1] * 0.125f,
                                   vals[2] * 0.125f, vals[3] * 0.125f);
            ((float4*)((float*)outp + (size_t)d * OUTD))[lane] = o;
        }
    }
}

// ---------------- launch ----------------------------------------------------
extern "C" void kernel_launch(void* const* d_in, const int* in_sizes, int n_in,
                              void* d_out, int out_size)
{
    const float* x   = (const float*)d_in[0];
    const float* W1  = (const float*)d_in[1];
    const float* al1 = (const float*)d_in[2];
    const float* ar1 = (const float*)d_in[3];
    const float* b1  = (const float*)d_in[4];
    const float* W2  = (const float*)d_in[5];
    const float* al2 = (const float*)d_in[6];
    const float* ar2 = (const float*)d_in[7];
    const float* b2  = (const float*)d_in[8];
    const int*   src = (const int*)d_in[9];
    const int*   dst = (const int*)d_in[10];
    float* out = (float*)d_out;

    __half *x16, *W1h, *W2h, *feat1, *agg1, *feat2;
    float *el, *er;
    cudaGetSymbolAddress((void**)&x16,   g_x16);
    cudaGetSymbolAddress((void**)&W1h,   g_W1_16);
    cudaGetSymbolAddress((void**)&W2h,   g_W2_16);
    cudaGetSymbolAddress((void**)&feat1, g_feat1);
    cudaGetSymbolAddress((void**)&agg1,  g_agg1);
    cudaGetSymbolAddress((void**)&feat2, g_feat2);
    cudaGetSymbolAddress((void**)&el,    g_el);
    cudaGetSymbolAddress((void**)&er,    g_er);

    static bool attrDone = false;
    if (!attrDone) {
        cudaFuncSetAttribute((const void*)gemm_att_wmma<INF_, C1, HIDD>,
                             cudaFuncAttributeMaxDynamicSharedMemorySize, 64 * C1 * 4);
        cudaFuncSetAttribute((const void*)gemm_att_wmma<C1, C2, OUTD>,
                             cudaFuncAttributeMaxDynamicSharedMemorySize, 64 * C2 * 4);
        attrDone = true;
    }

    const int eBlocks    = (EE + 255) / 256;
    const int gemmBlocks = NNP / 64;
    const int nodeBlocks = (NN + 7) / 8;

    // converts + cnt zero + csr dummy fill + dummy el (one grid)
    k_convert<<<(NN*INF_ + 255)/256, 256>>>(x, W1, W2);
    // CSR build (pad-to-4 rows)
    k_hist<<<eBlocks, 256>>>(dst);
    k_scan<<<1, 1024>>>();
    k_scatter<<<eBlocks, 256>>>(src, dst);

    // layer 1
    gemm_att_wmma<INF_, C1, HIDD><<<gemmBlocks, 256, 64*C1*4>>>(x16, W1h, al1, ar1,
                                                                feat1, el, er, NN);
    node_aggregate<C1, true, false><<<nodeBlocks, 256>>>(feat1, el, er, b1, agg1);

    // layer 2 (head-mean fused)
    gemm_att_wmma<C1, C2, OUTD><<<gemmBlocks, 256, 64*C2*4>>>(agg1, W2h, al2, ar2,
                                                              feat2, el, er, NN);
    node_aggregate<C2, false, true><<<nodeBlocks, 256>>>(feat2, el, er, b2, out);
}